// round 1
// baseline (speedup 1.0000x reference)
#include <cuda_runtime.h>
#include <cuda_bf16.h>
#include <math.h>

#define BATCH 16
#define FDIM  1024
#define NH    16
#define HDIM  64
#define LCTX  8192
#define HD    1024                      // NH*HDIM
#define CACHE_ELEMS (16ull*8192ull*1024ull)  // B*L*H*D = 134217728

// Scratch (no device allocation allowed -> __device__ globals)
__device__ float g_q[BATCH*HD];
__device__ float g_knew[BATCH*HD];
__device__ float g_vnew[BATCH*HD];
__device__ float g_attn[BATCH*HD];

__device__ __forceinline__ float bf16r(float x) {
    return __bfloat162float(__float2bfloat16(x));
}

// ---------------------------------------------------------------------------
// QKV projection: q/k/v[b,c] = sum_f x[b,f] * W[f,c] + bias[c]
// 3 mats x 8 col-blocks of 128 cols = 24 blocks, 128 threads.
// ---------------------------------------------------------------------------
__global__ void qkv_kernel(const float* __restrict__ x,
                           const float* __restrict__ Wq, const float* __restrict__ bq,
                           const float* __restrict__ Wk, const float* __restrict__ bk,
                           const float* __restrict__ Wv, const float* __restrict__ bv,
                           const int*   __restrict__ kv_idx,
                           float* __restrict__ out_idx) {
    const int mat = blockIdx.x >> 3;
    const int c   = ((blockIdx.x & 7) << 7) + threadIdx.x;   // 0..1023
    const float* W    = (mat == 0) ? Wq : ((mat == 1) ? Wk : Wv);
    const float* bias = (mat == 0) ? bq : ((mat == 1) ? bk : bv);
    float* dst        = (mat == 0) ? g_q : ((mat == 1) ? g_knew : g_vnew);

    __shared__ float xs[BATCH][128];
    float acc[BATCH];
#pragma unroll
    for (int b = 0; b < BATCH; b++) acc[b] = 0.f;

    for (int f0 = 0; f0 < FDIM; f0 += 128) {
        for (int i = threadIdx.x; i < BATCH * 128; i += 128)
            xs[i >> 7][i & 127] = x[(i >> 7) * FDIM + f0 + (i & 127)];
        __syncthreads();
#pragma unroll 4
        for (int j = 0; j < 128; j++) {
            float w = W[(size_t)(f0 + j) * HD + c];
#pragma unroll
            for (int b = 0; b < BATCH; b++) acc[b] += xs[b][j] * w;
        }
        __syncthreads();
    }
    float bb = bias[c];
#pragma unroll
    for (int b = 0; b < BATCH; b++) dst[b * HD + c] = acc[b] + bb;

    if (blockIdx.x == 0 && threadIdx.x < BATCH)
        out_idx[threadIdx.x] = (float)(kv_idx[threadIdx.x] + 1);
}

// ---------------------------------------------------------------------------
// Fused cache copy + ring-buffer row update (float4, one pass).
// which = 0 -> key cache (g_knew), 1 -> value cache (g_vnew).
// ---------------------------------------------------------------------------
__global__ void copy_update_kernel(const float4* __restrict__ src,
                                   float4* __restrict__ dst,
                                   const int* __restrict__ kv_idx,
                                   int which) {
    const float* newrow = which ? g_vnew : g_knew;
    size_t i = (size_t)blockIdx.x * 256 + threadIdx.x;   // float4 index
    int b   = (int)(i >> 21);                 // L*HD/4 = 2^21 float4 per batch
    int rem = (int)(i & ((1u << 21) - 1));
    int l   = rem >> 8;                       // HD/4 = 256 float4 per row
    float4 v;
    if (l == kv_idx[b])
        v = ((const float4*)newrow)[(b << 8) + (rem & 255)];
    else
        v = src[i];
    dst[i] = v;
}

// ---------------------------------------------------------------------------
// Decode attention for one (b,h) per block; 256 threads.
// Two-pass: logits row in smem, block softmax, then PV accumulation.
// Emulates reference bf16 rounding of q,k,v,probs and bf16 PV output.
// ---------------------------------------------------------------------------
__global__ void attn_kernel(const float* __restrict__ kcache,
                            const float* __restrict__ vcache,
                            const int* __restrict__ kv_idx) {
    const int h = blockIdx.x, b = blockIdx.y;
    int seq = kv_idx[b] + 1;
    if (seq > LCTX) seq = LCTX;

    __shared__ float logits[LCTX];
    __shared__ float qs[HDIM];
    __shared__ float red[256];

    const int tid = threadIdx.x, lane = tid & 31, w = tid >> 5;

    if (tid < HDIM) qs[tid] = bf16r(g_q[(b * NH + h) * HDIM + tid]);
    __syncthreads();
    const float q0 = qs[2 * lane], q1 = qs[2 * lane + 1];

    const float* kb = kcache + (size_t)b * LCTX * HD + h * HDIM;
    const int padded = (seq + 31) & ~31;

    // Pass 1: logits. Each warp does 4 rows per iter (interleaved reductions).
    for (int l0 = w * 4; l0 < padded; l0 += 32) {
        const float2 k0 = *(const float2*)(kb + (size_t)(l0 + 0) * HD + 2 * lane);
        const float2 k1 = *(const float2*)(kb + (size_t)(l0 + 1) * HD + 2 * lane);
        const float2 k2 = *(const float2*)(kb + (size_t)(l0 + 2) * HD + 2 * lane);
        const float2 k3 = *(const float2*)(kb + (size_t)(l0 + 3) * HD + 2 * lane);
        float d0 = q0 * bf16r(k0.x) + q1 * bf16r(k0.y);
        float d1 = q0 * bf16r(k1.x) + q1 * bf16r(k1.y);
        float d2 = q0 * bf16r(k2.x) + q1 * bf16r(k2.y);
        float d3 = q0 * bf16r(k3.x) + q1 * bf16r(k3.y);
#pragma unroll
        for (int off = 16; off > 0; off >>= 1) {
            d0 += __shfl_xor_sync(0xffffffffu, d0, off);
            d1 += __shfl_xor_sync(0xffffffffu, d1, off);
            d2 += __shfl_xor_sync(0xffffffffu, d2, off);
            d3 += __shfl_xor_sync(0xffffffffu, d3, off);
        }
        if (lane == 0) {
            const float s = 0.125f;   // 1/sqrt(64)
            if (l0 + 0 < seq) logits[l0 + 0] = d0 * s;
            if (l0 + 1 < seq) logits[l0 + 1] = d1 * s;
            if (l0 + 2 < seq) logits[l0 + 2] = d2 * s;
            if (l0 + 3 < seq) logits[l0 + 3] = d3 * s;
        }
    }
    __syncthreads();

    // Block max
    float m = -3.4e38f;
    for (int l = tid; l < seq; l += 256) m = fmaxf(m, logits[l]);
    red[tid] = m; __syncthreads();
    for (int s = 128; s > 0; s >>= 1) {
        if (tid < s) red[tid] = fmaxf(red[tid], red[tid + s]);
        __syncthreads();
    }
    m = red[0]; __syncthreads();

    // exp + block sum
    float sum = 0.f;
    for (int l = tid; l < seq; l += 256) {
        float e = expf(logits[l] - m);
        logits[l] = e;
        sum += e;
    }
    red[tid] = sum; __syncthreads();
    for (int s = 128; s > 0; s >>= 1) {
        if (tid < s) red[tid] += red[tid + s];
        __syncthreads();
    }
    const float inv = 1.f / red[0];
    __syncthreads();

    // Pass 2: PV accumulation. 4 row-groups x 64 dims.
    const int d = tid & 63, g = tid >> 6;
    const float* vb = vcache + (size_t)b * LCTX * HD + h * HDIM + d;
    float a0 = 0.f, a1 = 0.f, a2 = 0.f, a3 = 0.f;
    int l = g;
    for (; l + 12 < seq; l += 16) {
        a0 += bf16r(logits[l]      * inv) * bf16r(vb[(size_t)(l)      * HD]);
        a1 += bf16r(logits[l + 4]  * inv) * bf16r(vb[(size_t)(l + 4)  * HD]);
        a2 += bf16r(logits[l + 8]  * inv) * bf16r(vb[(size_t)(l + 8)  * HD]);
        a3 += bf16r(logits[l + 12] * inv) * bf16r(vb[(size_t)(l + 12) * HD]);
    }
    for (; l < seq; l += 4)
        a0 += bf16r(logits[l] * inv) * bf16r(vb[(size_t)l * HD]);
    red[tid] = a0 + a1 + a2 + a3;
    __syncthreads();
    if (g == 0) {
        float tot = red[d] + red[64 + d] + red[128 + d] + red[192 + d];
        g_attn[(b * NH + h) * HDIM + d] = bf16r(tot);   // einsum output is bf16
    }
}

// ---------------------------------------------------------------------------
// Output projection: y[b,f] = sum_hd attn[b,hd] * Wo[hd,f] + bo[f]
// ---------------------------------------------------------------------------
__global__ void proj_kernel(const float* __restrict__ Wo,
                            const float* __restrict__ bo,
                            float* __restrict__ y) {
    const int c = blockIdx.x * 128 + threadIdx.x;
    __shared__ float as[BATCH][128];
    float acc[BATCH];
#pragma unroll
    for (int b = 0; b < BATCH; b++) acc[b] = 0.f;

    for (int f0 = 0; f0 < HD; f0 += 128) {
        for (int i = threadIdx.x; i < BATCH * 128; i += 128)
            as[i >> 7][i & 127] = g_attn[(i >> 7) * HD + f0 + (i & 127)];
        __syncthreads();
#pragma unroll 4
        for (int j = 0; j < 128; j++) {
            float w = Wo[(size_t)(f0 + j) * FDIM + c];
#pragma unroll
            for (int b = 0; b < BATCH; b++) acc[b] += as[b][j] * w;
        }
        __syncthreads();
    }
    float bb = bo[c];
#pragma unroll
    for (int b = 0; b < BATCH; b++) y[b * FDIM + c] = acc[b] + bb;
}

// ---------------------------------------------------------------------------
extern "C" void kernel_launch(void* const* d_in, const int* in_sizes, int n_in,
                              void* d_out, int out_size) {
    const float* x        = (const float*)d_in[0];
    const float* kv_key   = (const float*)d_in[1];
    const float* kv_value = (const float*)d_in[2];
    const int*   kv_idx   = (const int*)  d_in[3];
    const float* Wq = (const float*)d_in[4];  const float* bq = (const float*)d_in[5];
    const float* Wk = (const float*)d_in[6];  const float* bk = (const float*)d_in[7];
    const float* Wv = (const float*)d_in[8];  const float* bv = (const float*)d_in[9];
    const float* Wo = (const float*)d_in[10]; const float* bo = (const float*)d_in[11];

    float* out     = (float*)d_out;
    float* out_y   = out;                                 // [B,F]
    float* out_key = out + (size_t)BATCH * FDIM;          // [B,L,H,D]
    float* out_val = out_key + CACHE_ELEMS;               // [B,L,H,D]
    float* out_idx = out_val + CACHE_ELEMS;               // [B] (as float)

    qkv_kernel<<<24, 128>>>(x, Wq, bq, Wk, bk, Wv, bv, kv_idx, out_idx);

    const int nblk = (int)(CACHE_ELEMS / 4 / 256);        // 131072
    copy_update_kernel<<<nblk, 256>>>((const float4*)kv_key,   (float4*)out_key, kv_idx, 0);
    copy_update_kernel<<<nblk, 256>>>((const float4*)kv_value, (float4*)out_val, kv_idx, 1);

    attn_kernel<<<dim3(NH, BATCH), 256>>>(out_key, out_val, kv_idx);

    proj_kernel<<<8, 128>>>(Wo, bo, out_y);
}

// round 2
// speedup vs baseline: 2.6419x; 2.6419x over previous
#include <cuda_runtime.h>
#include <cuda_bf16.h>
#include <math.h>

#define BATCH 16
#define FDIM  1024
#define NH    16
#define HDIM  64
#define LCTX  8192
#define HD    1024
#define CACHE_ELEMS (16ull*8192ull*1024ull)

// -------- scratch (device globals; no allocations allowed) --------
__device__ float g_q[BATCH*HD];
__device__ float g_knew[BATCH*HD];
__device__ float g_vnew[BATCH*HD];
__device__ float g_attn[BATCH*HD];
__device__ float g_logits[(size_t)BATCH*LCTX*NH];          // [b][l][h]  8MB
__device__ __nv_bfloat16 g_probs[(size_t)BATCH*LCTX*NH];   // [b][l][h]  4MB
__device__ float g_pv[(size_t)BATCH*256*HD];               // [b][chunk][1024] 16MB
__device__ float g_qkvp[3*8*BATCH*HD];                     // [mat][s][b][c] 1.5MB
__device__ float g_yp[8*BATCH*FDIM];                       // [s][b][c] 512KB

__device__ __forceinline__ float bf16r(float x) {
    return __bfloat162float(__float2bfloat16(x));
}

// ---------------------------------------------------------------------------
// QKV projection, 8-way split over F. grid (24, 8), 128 threads.
// ---------------------------------------------------------------------------
__global__ void qkv_part(const float* __restrict__ x,
                         const float* __restrict__ Wq,
                         const float* __restrict__ Wk,
                         const float* __restrict__ Wv) {
    const int mat = blockIdx.x >> 3;
    const int c   = ((blockIdx.x & 7) << 7) + threadIdx.x;
    const int s   = blockIdx.y;
    const int f0  = s * 128;
    const float* W = (mat == 0) ? Wq : ((mat == 1) ? Wk : Wv);

    __shared__ float xs[BATCH][128];
    for (int i = threadIdx.x; i < BATCH * 128; i += 128)
        xs[i >> 7][i & 127] = x[(i >> 7) * FDIM + f0 + (i & 127)];
    __syncthreads();

    float acc[BATCH];
#pragma unroll
    for (int b = 0; b < BATCH; b++) acc[b] = 0.f;
#pragma unroll 8
    for (int j = 0; j < 128; j++) {
        float w = W[(size_t)(f0 + j) * HD + c];
#pragma unroll
        for (int b = 0; b < BATCH; b++) acc[b] += xs[b][j] * w;
    }
#pragma unroll
    for (int b = 0; b < BATCH; b++)
        g_qkvp[(((mat * 8 + s) * BATCH) + b) * HD + c] = acc[b];
}

__global__ void qkv_combine(const float* __restrict__ bq,
                            const float* __restrict__ bk,
                            const float* __restrict__ bv,
                            const int*   __restrict__ kv_idx,
                            float* __restrict__ out_idx) {
    const int gid = blockIdx.x * 1024 + threadIdx.x;   // 48 blocks x 1024
    const int mat = gid >> 14;
    const int r   = gid & 16383;          // b*1024 + c
    const int c   = r & 1023;
    float acc = 0.f;
#pragma unroll
    for (int s = 0; s < 8; s++)
        acc += g_qkvp[((mat * 8 + s) * BATCH) * HD + r];
    const float* bias = (mat == 0) ? bq : ((mat == 1) ? bk : bv);
    float* dst        = (mat == 0) ? g_q : ((mat == 1) ? g_knew : g_vnew);
    dst[r] = acc + bias[c];
    if (blockIdx.x == 0 && threadIdx.x < BATCH)
        out_idx[threadIdx.x] = (float)(kv_idx[threadIdx.x] + 1);
}

// ---------------------------------------------------------------------------
// K-cache copy + ring update + logits, fused. grid (512, B), 256 threads.
// thread p: h = p>>4, covers dims [4*(p&15) .. ) of that head.
// ---------------------------------------------------------------------------
__global__ void key_copy_logits(const float4* __restrict__ src,
                                float4* __restrict__ dst,
                                const int* __restrict__ kv_idx) {
    const int b  = blockIdx.y;
    const int l0 = blockIdx.x * 16;
    const int p  = threadIdx.x;
    const int h  = p >> 4, d4 = p & 15;
    const int idx = __ldg(kv_idx + b);

    const float* qp = g_q + b * HD + p * 4;
    const float q0 = bf16r(qp[0]), q1 = bf16r(qp[1]);
    const float q2 = bf16r(qp[2]), q3 = bf16r(qp[3]);
    const float4 knew4 = ((const float4*)g_knew)[b * 256 + p];

    const size_t base = ((size_t)b * LCTX + l0) * 256 + p;
#pragma unroll
    for (int j = 0; j < 16; j++) {
        const int l = l0 + j;
        float4 v = src[base + (size_t)j * 256];
        if (l == idx) v = knew4;
        dst[base + (size_t)j * 256] = v;
        float d = q0 * bf16r(v.x) + q1 * bf16r(v.y)
                + q2 * bf16r(v.z) + q3 * bf16r(v.w);
        d += __shfl_down_sync(0xffffffffu, d, 8, 16);
        d += __shfl_down_sync(0xffffffffu, d, 4, 16);
        d += __shfl_down_sync(0xffffffffu, d, 2, 16);
        d += __shfl_down_sync(0xffffffffu, d, 1, 16);
        if (d4 == 0)
            g_logits[((size_t)b * LCTX + l) * NH + h] = d * 0.125f;
    }
}

// ---------------------------------------------------------------------------
// Softmax over [l] per (b,h). grid 16 (b), 1024 threads, coalesced [l][h].
// ---------------------------------------------------------------------------
__global__ void softmax_kernel(const int* __restrict__ kv_idx) {
    const int b = blockIdx.x;
    int seq = __ldg(kv_idx + b) + 1;
    if (seq > LCTX) seq = LCTX;
    const int t  = threadIdx.x;
    const int hl = t & 15;        // h
    const int li = t >> 4;        // 0..63 l-stripe

    __shared__ float red[64][17];
    const float* lg = g_logits + (size_t)b * LCTX * NH;

    float m = -3.4e38f;
    for (int l = li; l < seq; l += 64) m = fmaxf(m, lg[l * NH + hl]);
    red[li][hl] = m; __syncthreads();
    for (int s = 32; s > 0; s >>= 1) {
        if (li < s) red[li][hl] = fmaxf(red[li][hl], red[li + s][hl]);
        __syncthreads();
    }
    m = red[0][hl]; __syncthreads();

    float sum = 0.f;
    for (int l = li; l < seq; l += 64) sum += expf(lg[l * NH + hl] - m);
    red[li][hl] = sum; __syncthreads();
    for (int s = 32; s > 0; s >>= 1) {
        if (li < s) red[li][hl] += red[li + s][hl];
        __syncthreads();
    }
    const float inv = 1.f / red[0][hl];

    __nv_bfloat16* pb = g_probs + (size_t)b * LCTX * NH;
    for (int l = li; l < LCTX; l += 64) {
        float pr = (l < seq) ? expf(lg[l * NH + hl] - m) * inv : 0.f;
        pb[l * NH + hl] = __float2bfloat16(pr);
    }
}

// ---------------------------------------------------------------------------
// V-cache copy + ring update + PV partials, fused. grid (256, B), 256 threads.
// ---------------------------------------------------------------------------
__global__ void value_copy_pv(const float4* __restrict__ src,
                              float4* __restrict__ dst,
                              const int* __restrict__ kv_idx) {
    const int b     = blockIdx.y;
    const int chunk = blockIdx.x;
    const int l0    = chunk * 32;
    const int p     = threadIdx.x;
    const int h     = p >> 4;
    const int idx   = __ldg(kv_idx + b);

    __shared__ float pr[32 * 16];
    {
        const __nv_bfloat16* pp = g_probs + ((size_t)b * LCTX + l0) * NH;
        pr[p]       = __bfloat162float(pp[p]);
        pr[p + 256] = __bfloat162float(pp[p + 256]);
    }
    __syncthreads();

    const float4 vnew4 = ((const float4*)g_vnew)[b * 256 + p];
    const size_t base = ((size_t)b * LCTX + l0) * 256 + p;
    float a0 = 0.f, a1 = 0.f, a2 = 0.f, a3 = 0.f;
#pragma unroll
    for (int j = 0; j < 32; j++) {
        const int l = l0 + j;
        float4 v = src[base + (size_t)j * 256];
        if (l == idx) v = vnew4;
        dst[base + (size_t)j * 256] = v;
        const float w = pr[j * 16 + h];
        a0 += w * bf16r(v.x); a1 += w * bf16r(v.y);
        a2 += w * bf16r(v.z); a3 += w * bf16r(v.w);
    }
    float4 out; out.x = a0; out.y = a1; out.z = a2; out.w = a3;
    ((float4*)g_pv)[((size_t)b * 256 + chunk) * 256 + p] = out;
}

// ---------------------------------------------------------------------------
// Reduce PV partials -> g_attn (bf16-rounded). grid 16 (b), 1024 threads.
// ---------------------------------------------------------------------------
__global__ void pv_reduce() {
    const int b = blockIdx.x;
    const int t = threadIdx.x;
    const int p = t & 255;
    const int s = t >> 8;              // 0..3, each sums 64 chunks
    __shared__ float4 red[1024];

    const float4* pv = (const float4*)g_pv + (size_t)b * 256 * 256 + p;
    float4 acc; acc.x = acc.y = acc.z = acc.w = 0.f;
#pragma unroll 8
    for (int c = s * 64; c < s * 64 + 64; c++) {
        float4 v = pv[(size_t)c * 256];
        acc.x += v.x; acc.y += v.y; acc.z += v.z; acc.w += v.w;
    }
    red[t] = acc; __syncthreads();
    if (s == 0) {
        float4 r0 = red[p], r1 = red[p + 256], r2 = red[p + 512], r3 = red[p + 768];
        float* dst = g_attn + b * HD + p * 4;
        dst[0] = bf16r(r0.x + r1.x + r2.x + r3.x);
        dst[1] = bf16r(r0.y + r1.y + r2.y + r3.y);
        dst[2] = bf16r(r0.z + r1.z + r2.z + r3.z);
        dst[3] = bf16r(r0.w + r1.w + r2.w + r3.w);
    }
}

// ---------------------------------------------------------------------------
// Output projection, 8-way split over HD. grid (8, 8), 128 threads.
// ---------------------------------------------------------------------------
__global__ void proj_part(const float* __restrict__ Wo) {
    const int c  = blockIdx.x * 128 + threadIdx.x;
    const int s  = blockIdx.y;
    const int f0 = s * 128;

    __shared__ float as[BATCH][128];
    for (int i = threadIdx.x; i < BATCH * 128; i += 128)
        as[i >> 7][i & 127] = g_attn[(i >> 7) * HD + f0 + (i & 127)];
    __syncthreads();

    float acc[BATCH];
#pragma unroll
    for (int b = 0; b < BATCH; b++) acc[b] = 0.f;
#pragma unroll 8
    for (int j = 0; j < 128; j++) {
        float w = Wo[(size_t)(f0 + j) * FDIM + c];
#pragma unroll
        for (int b = 0; b < BATCH; b++) acc[b] += as[b][j] * w;
    }
#pragma unroll
    for (int b = 0; b < BATCH; b++)
        g_yp[(s * BATCH + b) * FDIM + c] = acc[b];
}

__global__ void proj_combine(const float* __restrict__ bo,
                             float* __restrict__ y) {
    const int b = blockIdx.x;          // grid 16, 1024 threads
    const int c = threadIdx.x;
    float acc = 0.f;
#pragma unroll
    for (int s = 0; s < 8; s++)
        acc += g_yp[(s * BATCH + b) * FDIM + c];
    y[b * FDIM + c] = acc + bo[c];
}

// ---------------------------------------------------------------------------
extern "C" void kernel_launch(void* const* d_in, const int* in_sizes, int n_in,
                              void* d_out, int out_size) {
    const float* x        = (const float*)d_in[0];
    const float* kv_key   = (const float*)d_in[1];
    const float* kv_value = (const float*)d_in[2];
    const int*   kv_idx   = (const int*)  d_in[3];
    const float* Wq = (const float*)d_in[4];  const float* bq = (const float*)d_in[5];
    const float* Wk = (const float*)d_in[6];  const float* bk = (const float*)d_in[7];
    const float* Wv = (const float*)d_in[8];  const float* bv = (const float*)d_in[9];
    const float* Wo = (const float*)d_in[10]; const float* bo = (const float*)d_in[11];

    float* out     = (float*)d_out;
    float* out_y   = out;
    float* out_key = out + (size_t)BATCH * FDIM;
    float* out_val = out_key + CACHE_ELEMS;
    float* out_idx = out_val + CACHE_ELEMS;

    qkv_part<<<dim3(24, 8), 128>>>(x, Wq, Wk, Wv);
    qkv_combine<<<48, 1024>>>(bq, bk, bv, kv_idx, out_idx);

    key_copy_logits<<<dim3(512, BATCH), 256>>>((const float4*)kv_key,
                                               (float4*)out_key, kv_idx);
    softmax_kernel<<<BATCH, 1024>>>(kv_idx);
    value_copy_pv<<<dim3(256, BATCH), 256>>>((const float4*)kv_value,
                                             (float4*)out_val, kv_idx);
    pv_reduce<<<BATCH, 1024>>>();

    proj_part<<<dim3(8, 8), 128>>>(Wo);
    proj_combine<<<BATCH, 1024>>>(bo, out_y);
}

// round 4
// speedup vs baseline: 2.8940x; 1.0954x over previous
#include <cuda_runtime.h>
#include <cuda_bf16.h>
#include <math.h>

#define BATCH 16
#define FDIM  1024
#define NH    16
#define HDIM  64
#define LCTX  8192
#define HD    1024
#define CACHE_ELEMS (16ull*8192ull*1024ull)

// -------- scratch (device globals; no allocations allowed) --------
__device__ float g_q[BATCH*HD];
__device__ float g_knew[BATCH*HD];
__device__ float g_vnew[BATCH*HD];
__device__ float g_attn[BATCH*HD];
__device__ float g_logits[(size_t)BATCH*NH*LCTX];          // [b][h][l]  8MB
__device__ __nv_bfloat16 g_probs[(size_t)BATCH*NH*LCTX];   // [b][h][l]  4MB
__device__ float4 g_pv4[(size_t)BATCH*128*256];            // [b][chunk][256xfloat4] 8MB

__device__ __forceinline__ float bf16r(float x) {
    return __bfloat162float(__float2bfloat16(x));
}

// ---------------------------------------------------------------------------
// QKV GEMM, single kernel. grid 192 = 3 mats x 64 col-blocks(16 cols).
// 256 threads: thread = (b, c_local). Full K=1024 per thread.
// ---------------------------------------------------------------------------
__global__ void qkv_gemm(const float* __restrict__ x,
                         const float* __restrict__ Wq, const float* __restrict__ Wk,
                         const float* __restrict__ Wv,
                         const float* __restrict__ bq, const float* __restrict__ bk,
                         const float* __restrict__ bv,
                         const int*   __restrict__ kv_idx,
                         float* __restrict__ out_idx) {
    const int mat = blockIdx.x >> 6;
    const int c0  = (blockIdx.x & 63) << 4;
    const float* W    = (mat == 0) ? Wq : ((mat == 1) ? Wk : Wv);
    const float* bias = (mat == 0) ? bq : ((mat == 1) ? bk : bv);
    float* dst        = (mat == 0) ? g_q : ((mat == 1) ? g_knew : g_vnew);

    const int tid = threadIdx.x;
    const int cl = tid & 15, b = tid >> 4;

    __shared__ float xs[BATCH][128];
    __shared__ float ws[16][132];

    float acc = 0.f;
    for (int f0 = 0; f0 < FDIM; f0 += 128) {
        __syncthreads();
        for (int i = tid; i < 2048; i += 256)
            xs[i >> 7][i & 127] = x[(i >> 7) * FDIM + f0 + (i & 127)];
        for (int i = tid; i < 2048; i += 256)
            ws[i & 15][i >> 4] = W[(size_t)(f0 + (i >> 4)) * HD + c0 + (i & 15)];
        __syncthreads();
        const float4* xv = (const float4*)xs[b];
        const float4* wv = (const float4*)ws[cl];
#pragma unroll
        for (int j = 0; j < 32; j++) {
            float4 a = xv[j], w = wv[j];
            acc += a.x * w.x + a.y * w.y + a.z * w.z + a.w * w.w;
        }
    }
    dst[b * HD + c0 + cl] = acc + bias[c0 + cl];
    if (blockIdx.x == 0 && tid < BATCH)
        out_idx[tid] = (float)(kv_idx[tid] + 1);
}

// ---------------------------------------------------------------------------
// K-cache copy + ring update + logits. grid (512, B), 256 threads, 16 rows.
// Logits written [b][h][l] with float4 stores from lane d4==0.
// ---------------------------------------------------------------------------
__global__ void key_copy_logits(const float4* __restrict__ src,
                                float4* __restrict__ dst,
                                const int* __restrict__ kv_idx) {
    const int b  = blockIdx.y;
    const int l0 = blockIdx.x * 16;
    const int p  = threadIdx.x;
    const int h  = p >> 4, d4 = p & 15;
    const int idx = __ldg(kv_idx + b);

    const float* qp = g_q + b * HD + p * 4;
    const float q0 = bf16r(qp[0]), q1 = bf16r(qp[1]);
    const float q2 = bf16r(qp[2]), q3 = bf16r(qp[3]);
    const float4 knew4 = ((const float4*)g_knew)[b * 256 + p];

    const size_t base = ((size_t)b * LCTX + l0) * 256 + p;
    float lg[16];
#pragma unroll
    for (int jj = 0; jj < 4; jj++) {
        float4 r0 = src[base + (size_t)(4 * jj + 0) * 256];
        float4 r1 = src[base + (size_t)(4 * jj + 1) * 256];
        float4 r2 = src[base + (size_t)(4 * jj + 2) * 256];
        float4 r3 = src[base + (size_t)(4 * jj + 3) * 256];
        if (l0 + 4 * jj + 0 == idx) r0 = knew4;
        if (l0 + 4 * jj + 1 == idx) r1 = knew4;
        if (l0 + 4 * jj + 2 == idx) r2 = knew4;
        if (l0 + 4 * jj + 3 == idx) r3 = knew4;
        dst[base + (size_t)(4 * jj + 0) * 256] = r0;
        dst[base + (size_t)(4 * jj + 1) * 256] = r1;
        dst[base + (size_t)(4 * jj + 2) * 256] = r2;
        dst[base + (size_t)(4 * jj + 3) * 256] = r3;
        float d0 = q0 * bf16r(r0.x) + q1 * bf16r(r0.y) + q2 * bf16r(r0.z) + q3 * bf16r(r0.w);
        float d1 = q0 * bf16r(r1.x) + q1 * bf16r(r1.y) + q2 * bf16r(r1.z) + q3 * bf16r(r1.w);
        float d2 = q0 * bf16r(r2.x) + q1 * bf16r(r2.y) + q2 * bf16r(r2.z) + q3 * bf16r(r2.w);
        float d3 = q0 * bf16r(r3.x) + q1 * bf16r(r3.y) + q2 * bf16r(r3.z) + q3 * bf16r(r3.w);
#pragma unroll
        for (int off = 8; off > 0; off >>= 1) {
            d0 += __shfl_down_sync(0xffffffffu, d0, off, 16);
            d1 += __shfl_down_sync(0xffffffffu, d1, off, 16);
            d2 += __shfl_down_sync(0xffffffffu, d2, off, 16);
            d3 += __shfl_down_sync(0xffffffffu, d3, off, 16);
        }
        lg[4 * jj + 0] = d0 * 0.125f;
        lg[4 * jj + 1] = d1 * 0.125f;
        lg[4 * jj + 2] = d2 * 0.125f;
        lg[4 * jj + 3] = d3 * 0.125f;
    }
    if (d4 == 0) {
        float4* lp = (float4*)(g_logits + ((size_t)(b * NH + h)) * LCTX + l0);
        lp[0] = make_float4(lg[0],  lg[1],  lg[2],  lg[3]);
        lp[1] = make_float4(lg[4],  lg[5],  lg[6],  lg[7]);
        lp[2] = make_float4(lg[8],  lg[9],  lg[10], lg[11]);
        lp[3] = make_float4(lg[12], lg[13], lg[14], lg[15]);
    }
}

// ---------------------------------------------------------------------------
// Softmax per (b,h) row, coalesced. grid (NH, B) = 256 blocks, 512 threads.
// ---------------------------------------------------------------------------
__global__ void softmax_kernel(const int* __restrict__ kv_idx) {
    const int h = blockIdx.x, b = blockIdx.y;
    int seq = __ldg(kv_idx + b) + 1;
    if (seq > LCTX) seq = LCTX;
    const int tid = threadIdx.x;

    __shared__ float ex[LCTX];
    __shared__ float red[512];

    const float4* lg4 = (const float4*)(g_logits + ((size_t)(b * NH + h)) * LCTX);
    const float NEG = -3.402823466e38f;

    float m = NEG;
#pragma unroll 4
    for (int i = tid; i < 2048; i += 512) {
        float4 v = lg4[i];
        const int l = i * 4;
        if (l + 0 >= seq) v.x = NEG;
        if (l + 1 >= seq) v.y = NEG;
        if (l + 2 >= seq) v.z = NEG;
        if (l + 3 >= seq) v.w = NEG;
        ((float4*)ex)[i] = v;
        m = fmaxf(m, fmaxf(fmaxf(v.x, v.y), fmaxf(v.z, v.w)));
    }
    red[tid] = m; __syncthreads();
    for (int s = 256; s > 0; s >>= 1) {
        if (tid < s) red[tid] = fmaxf(red[tid], red[tid + s]);
        __syncthreads();
    }
    m = red[0]; __syncthreads();

    float sum = 0.f;
#pragma unroll 4
    for (int i = tid; i < 2048; i += 512) {
        float4 v = ((float4*)ex)[i];
        v.x = expf(v.x - m); v.y = expf(v.y - m);
        v.z = expf(v.z - m); v.w = expf(v.w - m);
        ((float4*)ex)[i] = v;
        sum += v.x + v.y + v.z + v.w;
    }
    red[tid] = sum; __syncthreads();
    for (int s = 256; s > 0; s >>= 1) {
        if (tid < s) red[tid] += red[tid + s];
        __syncthreads();
    }
    const float inv = 1.f / red[0];

    uint2* pb = (uint2*)(g_probs + ((size_t)(b * NH + h)) * LCTX);
#pragma unroll 4
    for (int i = tid; i < 2048; i += 512) {
        float4 v = ((float4*)ex)[i];
        __nv_bfloat162 p0 = __floats2bfloat162_rn(v.x * inv, v.y * inv);
        __nv_bfloat162 p1 = __floats2bfloat162_rn(v.z * inv, v.w * inv);
        uint2 u;
        u.x = *(unsigned int*)&p0;
        u.y = *(unsigned int*)&p1;
        pb[i] = u;
    }
}

// ---------------------------------------------------------------------------
// V-cache copy + ring update + PV partials. grid (128, B), 256 threads, 64 rows.
// ---------------------------------------------------------------------------
__global__ void value_copy_pv(const float4* __restrict__ src,
                              float4* __restrict__ dst,
                              const int* __restrict__ kv_idx) {
    const int b     = blockIdx.y;
    const int chunk = blockIdx.x;
    const int l0    = chunk * 64;
    const int p     = threadIdx.x;
    const int h     = p >> 4;
    const int idx   = __ldg(kv_idx + b);

    __shared__ float pr[16][64];
    {
        const int hh = p >> 4, ii = p & 15;
        const uint2* prow = (const uint2*)(g_probs + ((size_t)(b * NH + hh)) * LCTX + l0);
        uint2 u = prow[ii];
        pr[hh][ii * 4 + 0] = __uint_as_float(u.x << 16);
        pr[hh][ii * 4 + 1] = __uint_as_float(u.x & 0xffff0000u);
        pr[hh][ii * 4 + 2] = __uint_as_float(u.y << 16);
        pr[hh][ii * 4 + 3] = __uint_as_float(u.y & 0xffff0000u);
    }
    __syncthreads();

    const float4 vnew4 = ((const float4*)g_vnew)[b * 256 + p];
    const size_t base = ((size_t)b * LCTX + l0) * 256 + p;
    float a0 = 0.f, a1 = 0.f, a2 = 0.f, a3 = 0.f;
#pragma unroll
    for (int jj = 0; jj < 16; jj++) {
        float4 r0 = src[base + (size_t)(4 * jj + 0) * 256];
        float4 r1 = src[base + (size_t)(4 * jj + 1) * 256];
        float4 r2 = src[base + (size_t)(4 * jj + 2) * 256];
        float4 r3 = src[base + (size_t)(4 * jj + 3) * 256];
        if (l0 + 4 * jj + 0 == idx) r0 = vnew4;
        if (l0 + 4 * jj + 1 == idx) r1 = vnew4;
        if (l0 + 4 * jj + 2 == idx) r2 = vnew4;
        if (l0 + 4 * jj + 3 == idx) r3 = vnew4;
        dst[base + (size_t)(4 * jj + 0) * 256] = r0;
        dst[base + (size_t)(4 * jj + 1) * 256] = r1;
        dst[base + (size_t)(4 * jj + 2) * 256] = r2;
        dst[base + (size_t)(4 * jj + 3) * 256] = r3;
        const float w0 = pr[h][4 * jj + 0], w1 = pr[h][4 * jj + 1];
        const float w2 = pr[h][4 * jj + 2], w3 = pr[h][4 * jj + 3];
        a0 += w0 * bf16r(r0.x) + w1 * bf16r(r1.x) + w2 * bf16r(r2.x) + w3 * bf16r(r3.x);
        a1 += w0 * bf16r(r0.y) + w1 * bf16r(r1.y) + w2 * bf16r(r2.y) + w3 * bf16r(r3.y);
        a2 += w0 * bf16r(r0.z) + w1 * bf16r(r1.z) + w2 * bf16r(r2.z) + w3 * bf16r(r3.z);
        a3 += w0 * bf16r(r0.w) + w1 * bf16r(r1.w) + w2 * bf16r(r2.w) + w3 * bf16r(r3.w);
    }
    float4 out; out.x = a0; out.y = a1; out.z = a2; out.w = a3;
    g_pv4[((size_t)(b * 128 + chunk)) * 256 + p] = out;
}

// ---------------------------------------------------------------------------
// Reduce PV partials -> g_attn (bf16-rounded). grid 16, 256 threads.
// ---------------------------------------------------------------------------
__global__ void pv_reduce() {
    const int b = blockIdx.x;
    const int p = threadIdx.x;
    float4 acc; acc.x = acc.y = acc.z = acc.w = 0.f;
    const float4* pv = g_pv4 + (size_t)b * 128 * 256 + p;
#pragma unroll 8
    for (int c = 0; c < 128; c++) {
        float4 v = pv[(size_t)c * 256];
        acc.x += v.x; acc.y += v.y; acc.z += v.z; acc.w += v.w;
    }
    float* d = g_attn + b * HD + p * 4;
    d[0] = bf16r(acc.x); d[1] = bf16r(acc.y);
    d[2] = bf16r(acc.z); d[3] = bf16r(acc.w);
}

// ---------------------------------------------------------------------------
// Output projection, single kernel. grid 64 col-blocks, 256 threads.
// ---------------------------------------------------------------------------
__global__ void proj_gemm(const float* __restrict__ Wo,
                          const float* __restrict__ bo,
                          float* __restrict__ y) {
    const int c0 = blockIdx.x << 4;
    const int tid = threadIdx.x;
    const int cl = tid & 15, b = tid >> 4;

    __shared__ float as[BATCH][128];
    __shared__ float ws[16][132];

    float acc = 0.f;
    for (int f0 = 0; f0 < HD; f0 += 128) {
        __syncthreads();
        for (int i = tid; i < 2048; i += 256)
            as[i >> 7][i & 127] = g_attn[(i >> 7) * HD + f0 + (i & 127)];
        for (int i = tid; i < 2048; i += 256)
            ws[i & 15][i >> 4] = Wo[(size_t)(f0 + (i >> 4)) * FDIM + c0 + (i & 15)];
        __syncthreads();
        const float4* xv = (const float4*)as[b];
        const float4* wv = (const float4*)ws[cl];
#pragma unroll
        for (int j = 0; j < 32; j++) {
            float4 a = xv[j], w = wv[j];
            acc += a.x * w.x + a.y * w.y + a.z * w.z + a.w * w.w;
        }
    }
    y[b * FDIM + c0 + cl] = acc + bo[c0 + cl];
}

// ---------------------------------------------------------------------------
extern "C" void kernel_launch(void* const* d_in, const int* in_sizes, int n_in,
                              void* d_out, int out_size) {
    const float* x        = (const float*)d_in[0];
    const float* kv_key   = (const float*)d_in[1];
    const float* kv_value = (const float*)d_in[2];
    const int*   kv_idx   = (const int*)  d_in[3];
    const float* Wq = (const float*)d_in[4];  const float* bq = (const float*)d_in[5];
    const float* Wk = (const float*)d_in[6];  const float* bk = (const float*)d_in[7];
    const float* Wv = (const float*)d_in[8];  const float* bv = (const float*)d_in[9];
    const float* Wo = (const float*)d_in[10]; const float* bo = (const float*)d_in[11];

    float* out     = (float*)d_out;
    float* out_y   = out;
    float* out_key = out + (size_t)BATCH * FDIM;
    float* out_val = out_key + CACHE_ELEMS;
    float* out_idx = out_val + CACHE_ELEMS;

    qkv_gemm<<<192, 256>>>(x, Wq, Wk, Wv, bq, bk, bv, kv_idx, out_idx);

    key_copy_logits<<<dim3(512, BATCH), 256>>>((const float4*)kv_key,
                                               (float4*)out_key, kv_idx);
    softmax_kernel<<<dim3(NH, BATCH), 512>>>(kv_idx);
    value_copy_pv<<<dim3(128, BATCH), 256>>>((const float4*)kv_value,
                                             (float4*)out_val, kv_idx);
    pv_reduce<<<BATCH, 256>>>();

    proj_gemm<<<64, 256>>>(Wo, bo, out_y);
}